// round 12
// baseline (speedup 1.0000x reference)
#include <cuda_runtime.h>
#include <cstdint>

#define BB 64
#define SS 2048
#define II 64
#define HH 128
#define CH 16
#define NCH (SS/CH)
#define MROWS (BB*SS)
#define NHELP 20

typedef unsigned long long ull;

// Scratch + flags (no runtime allocation allowed).
__device__ __align__(256) float g_seq0[(size_t)MROWS * HH];  // out0 (cols 64..127 used)
__device__ __align__(256) float g_xw0 [(size_t)MROWS * HH];  // x @ w0 (helpers)
__device__ __align__(256) float g_xw1p[(size_t)MROWS * HH];  // out0[:, :64] @ w1[:64,:]
__device__ unsigned g_flagH[BB];
__device__ unsigned g_flagP[BB];

#define BAR_SYNC(id, cnt)   asm volatile("bar.sync %0, %1;"   :: "r"(id), "r"(cnt) : "memory")
#define BAR_ARRIVE(id, cnt) asm volatile("bar.arrive %0, %1;" :: "r"(id), "r"(cnt) : "memory")

// ---------------- packed f32x2 helpers (sm_100+) ----------------
__device__ __forceinline__ ull packf2(float lo, float hi) {
    ull r; asm("mov.b64 %0, {%1, %2};" : "=l"(r) : "f"(lo), "f"(hi)); return r;
}
__device__ __forceinline__ float2 unpackf2(ull v) {
    float2 r; asm("mov.b64 {%0, %1}, %2;" : "=f"(r.x), "=f"(r.y) : "l"(v)); return r;
}
__device__ __forceinline__ ull ffma2(ull a, ull b, ull c) {
    ull d; asm("fma.rn.f32x2 %0, %1, %2, %3;" : "=l"(d) : "l"(a), "l"(b), "l"(c)); return d;
}
__device__ __forceinline__ ull addf2(ull a, ull b) {
    ull d; asm("add.rn.f32x2 %0, %1, %2;" : "=l"(d) : "l"(a), "l"(b)); return d;
}
__device__ __forceinline__ void lds_v2u64(ull &p0, ull &p1, uint32_t addr) {
    asm volatile("ld.shared.v2.u64 {%0, %1}, [%2];" : "=l"(p0), "=l"(p1) : "r"(addr));
}
__device__ __forceinline__ float ex2f(float x) {
    float r; asm("ex2.approx.ftz.f32 %0, %1;" : "=f"(r) : "f"(x)); return r;
}
__device__ __forceinline__ float rcpf(float x) {
    float r; asm("rcp.approx.ftz.f32 %0, %1;" : "=f"(r) : "f"(x)); return r;
}
__device__ __forceinline__ float sigmoidf_(float x) {
    return rcpf(1.0f + ex2f(-1.4426950408889634f * x));
}
__device__ __forceinline__ unsigned ld_acquire(const unsigned* p) {
    unsigned v;
    asm volatile("ld.acquire.gpu.global.u32 %0, [%1];" : "=r"(v) : "l"(p) : "memory");
    return v;
}
__device__ __forceinline__ void st_release(unsigned* p, unsigned v) {
    asm volatile("st.release.gpu.global.u32 [%0], %1;" :: "l"(p), "r"(v) : "memory");
}

__global__ void zero_flags() {
    if (threadIdx.x < BB) { g_flagH[threadIdx.x] = 0; g_flagP[threadIdx.x] = 0; }
}

// 64-value half-dot, 2-way split (32 vals/thread): 4 iters x (2 LDS.128 + 4 ffma2).
__device__ __forceinline__ float halfdot64(uint32_t base, const ull* wr) {
    ull z = packf2(0.f, 0.f);
    ull a0 = z, a1 = z, a2 = z, a3 = z;
#pragma unroll
    for (int i = 0; i < 4; i++) {
        ull p0, p1, p2, p3;
        lds_v2u64(p0, p1, base + (uint32_t)(i * 32));
        lds_v2u64(p2, p3, base + (uint32_t)(i * 32 + 16));
        a0 = ffma2(p0, wr[4 * i],     a0);
        a1 = ffma2(p1, wr[4 * i + 1], a1);
        a2 = ffma2(p2, wr[4 * i + 2], a2);
        a3 = ffma2(p3, wr[4 * i + 3], a3);
    }
    float2 f = unpackf2(addf2(addf2(a0, a1), addf2(a2, a3)));
    return f.x + f.y;
}

// ================= SCAN warps (tid >= 256, high wid) =================
// Thread (q,c): q=lane>>4 (k-half), c=warp*16+(lane&15). ureg = u[64q:64q+64, c].
// xw read from xw_s (filled by proj warps). PROD: also writes h rows into the
// hring (cols<64, for proj's xw1p dot) and out0 upper half.
// hring-ready handshake uses PARITY barriers 8/9 (scan arrive, proj sync):
// double-arrive into one generation is impossible because scan's next arrival
// to the same ID is gated behind proj's bar2 arrival, which follows its sync.
template<bool PROD>
__device__ __forceinline__ void scan_warps(
    float* hs, float* hring, const float* xw_s,
    const float* __restrict__ u,
    const float* bg, const float* bu,
    const float* zeta, const float* nu,
    const float* lambd, const float* gamma,
    float* __restrict__ outp, float* __restrict__ hl)
{
    const int tid  = threadIdx.x;
    const int lane = tid & 31;
    const int s    = tid - 256;
    const int wp   = s >> 5;
    const int q    = lane >> 4;
    const int c    = wp * 16 + (lane & 15);

    ull ureg[32];
#pragma unroll
    for (int m = 0; m < 32; m++) {
        int k0 = 64 * q + 2 * m;
        ureg[m] = packf2(u[(size_t)k0 * HH + c], u[(size_t)(k0 + 1) * HH + c]);
    }
    const float sz = sigmoidf_(zeta[0]);
    const float sn = sigmoidf_(nu[0]);
    float gc = gamma[0];
    gc = fminf(fmaxf(gc, 0.0f), 1.0f);
    const float c1   = (1.0f - gc) * lambd[0];
    const float szsn = sz + sn;
    const float bgs  = -1.4426950408889634f * bg[c];
    const float bus  =  2.8853900817779268f * bu[c];

    const uint32_t hb = (uint32_t)__cvta_generic_to_shared(hs);
    const uint32_t qoffH = (uint32_t)(q * 68 * 4);

    if (s < HH) hs[(s >> 6) * 68 + (s & 63)] = 0.0f;
    float hprev = 0.0f;
    BAR_SYNC(1, 256);

    for (int ch = 0; ch < NCH; ch++) {
        const int p = ch & 1;
        BAR_SYNC(2 + p, 512);                 // xw[p] ready
        float xwv[CH];
        const float* xwb = xw_s + (size_t)p * CH * HH + c;
#pragma unroll
        for (int d = 0; d < CH; d++) xwv[d] = xwb[d * HH];
        float* hrb = hring + (size_t)p * CH * 68;
#pragma unroll
        for (int d = 0; d < CH; d++) {
            const int t = ch * CH + d;
            const uint32_t ra = hb + ((t & 1) ? 544u : 0u) + qoffH;
            ull z0 = packf2(0.f, 0.f);
            ull a0 = z0, a1 = z0, a2 = z0, a3 = z0;
#pragma unroll
            for (int i = 0; i < 8; i++) {
                ull p0, p1, p2, p3;
                lds_v2u64(p0, p1, ra + (uint32_t)(i * 32));
                lds_v2u64(p2, p3, ra + (uint32_t)(i * 32 + 16));
                a0 = ffma2(p0, ureg[4 * i],     a0);
                a1 = ffma2(p1, ureg[4 * i + 1], a1);
                a2 = ffma2(p2, ureg[4 * i + 2], a2);
                a3 = ffma2(p3, ureg[4 * i + 3], a3);
            }
            float2 f = unpackf2(addf2(addf2(a0, a1), addf2(a2, a3)));
            float part = f.x + f.y;
            float pre = part + __shfl_xor_sync(0xffffffffu, part, 16) + xwv[d];

            float z  = rcpf(1.0f + ex2f(fmaf(-1.4426950408889634f, pre, bgs)));
            float hh = 1.0f - 2.0f * rcpf(1.0f + ex2f(fmaf(2.8853900817779268f, pre, bus)));
            float t1 = fmaf(-sz, hh, hprev);
            float hn = fmaf(z, t1, szsn * hh);
            float hc = fmaf(gc, hn, c1);

            if (lane < 16) {
                hs[((t & 1) ^ 1) * 136 + (c >> 6) * 68 + (c & 63)] = hc;
                if (PROD) {
                    if (wp < 4) hrb[d * 68 + c] = hc;           // cols 0..63
                    else        outp[(size_t)t * HH + c] = hc;  // out0 cols 64..127
                } else {
                    outp[(size_t)t * HH + c] = hc;              // out1 all cols
                }
            }
            hprev = hc;
            BAR_SYNC(1, 256);
        }
        if (PROD) {
            __threadfence();
            BAR_ARRIVE(8 + p, 512);           // hring[p] + out0 chunk ch done
        }
        BAR_ARRIVE(4 + p, 512);               // xw[p] free
    }
    if (lane < 16) hl[c] = hprev;
}

// ================= Producer proj warps (tid < 256) =================
// Per chunk ch: spin flagH; LDG xw0 chunk -> xw_s[p]; then compute xw1p for
// chunk ch-1 from hring (k<64 half of out0 @ w1), STG g_xw1p, release flagP.
__device__ __forceinline__ void proj_producer(
    float* hring, float* xw_s,
    const float* __restrict__ xw0b,   // g_xw0 + b*S*H
    const float* __restrict__ w1,
    float* __restrict__ xw1pb,        // g_xw1p + b*S*H
    const unsigned* flagH, unsigned* flagP)
{
    const int tid  = threadIdx.x;
    const int lane = tid & 31;
    const int wp2  = tid >> 5;
    const int qp   = lane >> 4;
    const int cp   = wp2 * 16 + (lane & 15);

    ull wreg[16];                     // w1[32*qp + .. , cp], k in [0,64)
#pragma unroll
    for (int m = 0; m < 16; m++) {
        int k0 = 32 * qp + 2 * m;
        wreg[m] = packf2(w1[(size_t)k0 * HH + cp], w1[(size_t)(k0 + 1) * HH + cp]);
    }
    const int rowd2 = tid >> 4;       // 0..15
    const int e2    = (tid & 15) * 8; // 0..120
    const uint32_t hrb = (uint32_t)__cvta_generic_to_shared(hring);

    for (int ch = 0; ch < NCH; ch++) {
        const int p = ch & 1;
        if (tid == 0) {
            while (ld_acquire(flagH) < (unsigned)((ch + 1) * CH)) { }
        }
        BAR_SYNC(7, 256);
        float4 r0 = __ldcg(reinterpret_cast<const float4*>(
            xw0b + (size_t)(ch * CH + rowd2) * HH + e2));
        float4 r1 = __ldcg(reinterpret_cast<const float4*>(
            xw0b + (size_t)(ch * CH + rowd2) * HH + e2 + 4));
        if (ch >= 2) BAR_SYNC(4 + p, 512);    // xw_s[p] free
        *reinterpret_cast<float4*>(&xw_s[(size_t)(p * CH + rowd2) * HH + e2])     = r0;
        *reinterpret_cast<float4*>(&xw_s[(size_t)(p * CH + rowd2) * HH + e2 + 4]) = r1;
        BAR_ARRIVE(2 + p, 512);               // xw[p] ready

        if (ch >= 1) {
            const int pm = (ch - 1) & 1;
            BAR_SYNC(8 + pm, 512);            // scan finished chunk ch-1
            const uint32_t base = hrb + (uint32_t)(pm * CH * 68 * 4)
                                + (uint32_t)(qp * 128);
#pragma unroll
            for (int d = 0; d < CH; d++) {
                float pp = halfdot64(base + (uint32_t)(d * 68 * 4), wreg);
                pp += __shfl_xor_sync(0xffffffffu, pp, 16);
                if (lane < 16)
                    xw1pb[(size_t)((ch - 1) * CH + d) * HH + cp] = pp;
            }
            __threadfence();
            if (tid == 0) st_release(flagP, (unsigned)(ch * CH));
        }
    }
    // epilogue: last chunk's xw1p
    {
        const int pm = (NCH - 1) & 1;
        BAR_SYNC(8 + pm, 512);
        const uint32_t base = hrb + (uint32_t)(pm * CH * 68 * 4)
                            + (uint32_t)(qp * 128);
#pragma unroll
        for (int d = 0; d < CH; d++) {
            float pp = halfdot64(base + (uint32_t)(d * 68 * 4), wreg);
            pp += __shfl_xor_sync(0xffffffffu, pp, 16);
            if (lane < 16)
                xw1pb[(size_t)((NCH - 1) * CH + d) * HH + cp] = pp;
        }
        __threadfence();
        if (tid == 0) st_release(flagP, (unsigned)SS);
    }
}

// ================= Consumer proj warps (tid < 256) =================
// Per chunk ch: spin flagP; stage out0 cols [64,128) into xt; dot k in [64,128)
// vs w1; add prefetched xw1p; write xw_s.
__device__ __forceinline__ void proj_consumer(
    float* xt, float* xw_s,
    const float* __restrict__ seq0b,  // g_seq0 + b*S*H
    const float* __restrict__ w1,
    const float* __restrict__ xw1pb,  // g_xw1p + b*S*H
    const unsigned* flagP)
{
    const int tid  = threadIdx.x;
    const int lane = tid & 31;
    const int wp2  = tid >> 5;
    const int qp   = lane >> 4;
    const int cp   = wp2 * 16 + (lane & 15);

    ull wreg[16];                     // w1[64 + 32*qp + .. , cp]
#pragma unroll
    for (int m = 0; m < 16; m++) {
        int k0 = 64 + 32 * qp + 2 * m;
        wreg[m] = packf2(w1[(size_t)k0 * HH + cp], w1[(size_t)(k0 + 1) * HH + cp]);
    }
    const int rowd = tid >> 4;        // 0..15
    const int e    = (tid & 15) * 4;  // 0..60
    const uint32_t xb = (uint32_t)__cvta_generic_to_shared(xt);

    for (int ch = 0; ch < NCH; ch++) {
        const int p = ch & 1;
        if (tid == 0) {
            while (ld_acquire(flagP) < (unsigned)((ch + 1) * CH)) { }
        }
        BAR_SYNC(7, 256);                     // flag fan-out; prev dot done
        float4 s4 = __ldcg(reinterpret_cast<const float4*>(
            seq0b + (size_t)(ch * CH + rowd) * HH + 64 + e));
        float xp[CH];
        if (lane < 16) {
#pragma unroll
            for (int d = 0; d < CH; d++)
                xp[d] = __ldcg(xw1pb + (size_t)(ch * CH + d) * HH + cp);
        }
        *reinterpret_cast<float4*>(&xt[rowd * 68 + e]) = s4;
        if (ch >= 2) BAR_SYNC(4 + p, 512);    // xw_s[p] free
        BAR_SYNC(7, 256);                     // tile staged
        const uint32_t base = xb + (uint32_t)(qp * 128);
#pragma unroll
        for (int d = 0; d < CH; d++) {
            float pp = halfdot64(base + (uint32_t)(d * 68 * 4), wreg);
            pp += __shfl_xor_sync(0xffffffffu, pp, 16);
            if (lane < 16)
                xw_s[(size_t)(p * CH + d) * HH + cp] = pp + xp[d];
        }
        BAR_ARRIVE(2 + p, 512);               // xw[p] ready
    }
}

// ================= Helper CTA: xw0 = x @ w0 (no upstream deps) =================
__device__ __forceinline__ void helper_cta(
    float* xh, const float* __restrict__ x, const float* __restrict__ w0,
    int base, int cnt)
{
    const int tid  = threadIdx.x;
    const int lane = tid & 31;
    const int wp   = tid >> 5;
    const int q    = lane >> 3;            // 4-way k-split of 64
    const int cw   = wp * 8 + (lane & 7);  // 16 warps x 8 = 128 cols

    ull wreg[8];
#pragma unroll
    for (int m = 0; m < 8; m++) {
        int k0 = 16 * q + 2 * m;
        wreg[m] = packf2(w0[(size_t)k0 * HH + cw], w0[(size_t)(k0 + 1) * HH + cw]);
    }
    const uint32_t hb = (uint32_t)__cvta_generic_to_shared(xh);
    const int rowd = tid >> 4;             // 0..15 (tid<256)
    const int e    = (tid & 15) * 4;       // 0..60

    for (int ch = 0; ch < NCH; ch++) {
        for (int j = 0; j < cnt; j++) {
            const int b = base + j;
            float4 s4 = make_float4(0.f, 0.f, 0.f, 0.f);
            if (tid < 256)
                s4 = __ldcg(reinterpret_cast<const float4*>(
                    x + (size_t)b * SS * II + (size_t)(ch * CH + rowd) * II + e));
            __syncthreads();               // prev dot done
            if (tid < 256)
                *reinterpret_cast<float4*>(&xh[rowd * 68 + e]) = s4;
            __syncthreads();
            float* outb = g_xw0 + (size_t)b * SS * HH;
#pragma unroll
            for (int d = 0; d < CH; d++) {
                const uint32_t bse = hb + (uint32_t)(d * 68 * 4) + (uint32_t)(q * 64);
                ull z0 = packf2(0.f, 0.f);
                ull b0 = z0, b1 = z0, b2 = z0, b3 = z0;
#pragma unroll
                for (int i = 0; i < 2; i++) {
                    ull p0, p1, p2, p3;
                    lds_v2u64(p0, p1, bse + (uint32_t)(i * 32));
                    lds_v2u64(p2, p3, bse + (uint32_t)(i * 32 + 16));
                    b0 = ffma2(p0, wreg[4 * i],     b0);
                    b1 = ffma2(p1, wreg[4 * i + 1], b1);
                    b2 = ffma2(p2, wreg[4 * i + 2], b2);
                    b3 = ffma2(p3, wreg[4 * i + 3], b3);
                }
                float2 f = unpackf2(addf2(addf2(b0, b1), addf2(b2, b3)));
                float pp = f.x + f.y;
                pp += __shfl_xor_sync(0xffffffffu, pp, 8);
                pp += __shfl_xor_sync(0xffffffffu, pp, 16);
                if (lane < 8) outb[(size_t)(ch * CH + d) * HH + cw] = pp;
            }
            __threadfence();
            __syncthreads();
            if (tid == 0) st_release(&g_flagH[b], (unsigned)((ch + 1) * CH));
        }
    }
}

// ================= fused persistent kernel =================
__global__ void __launch_bounds__(512, 1) fused_grnn(
    const float* __restrict__ x,
    const float* __restrict__ u0, const float* __restrict__ w0,
    const float* __restrict__ bg0, const float* __restrict__ bu0,
    const float* __restrict__ zeta0, const float* __restrict__ nu0,
    const float* __restrict__ lambd0, const float* __restrict__ gamma0,
    const float* __restrict__ u1, const float* __restrict__ w1,
    const float* __restrict__ bg1, const float* __restrict__ bu1,
    const float* __restrict__ zeta1, const float* __restrict__ nu1,
    const float* __restrict__ lambd1, const float* __restrict__ gamma1,
    float* __restrict__ out1, float* __restrict__ hn)
{
    __shared__ __align__(16) float hs[2 * 136];
    __shared__ __align__(16) float hring[2 * CH * 68];
    __shared__ __align__(16) float xt[CH * 68];
    __shared__ __align__(16) float xw_s[2 * CH * HH];

    const int rank = blockIdx.x;
    if (rank < BB) {
        const int b = rank;
        if (threadIdx.x >= 256) {
            scan_warps<true>(hs, hring, xw_s, u0,
                bg0, bu0, zeta0, nu0, lambd0, gamma0,
                g_seq0 + (size_t)b * SS * HH, hn + (size_t)b * HH);
        } else {
            proj_producer(hring, xw_s,
                g_xw0 + (size_t)b * SS * HH, w1,
                g_xw1p + (size_t)b * SS * HH,
                &g_flagH[b], &g_flagP[b]);
        }
    } else if (rank < 2 * BB) {
        const int b = rank - BB;
        if (threadIdx.x >= 256) {
            scan_warps<false>(hs, hring, xw_s, u1,
                bg1, bu1, zeta1, nu1, lambd1, gamma1,
                out1 + (size_t)b * SS * HH, hn + (size_t)(BB + b) * HH);
        } else {
            proj_consumer(xt, xw_s,
                g_seq0 + (size_t)b * SS * HH, w1,
                g_xw1p + (size_t)b * SS * HH,
                &g_flagP[b]);
        }
    } else {
        const int i = rank - 2 * BB;          // 0..19
        const int base = (i < 4) ? 4 * i : 16 + 3 * (i - 4);
        const int cnt  = (i < 4) ? 4 : 3;
        helper_cta(xt /*reuse*/, x, w0, base, cnt);
    }
}

// ---------------- launch ----------------
extern "C" void kernel_launch(void* const* d_in, const int* in_sizes, int n_in,
                              void* d_out, int out_size)
{
    const float* x      = (const float*)d_in[0];
    const float* w0     = (const float*)d_in[1];
    const float* u0     = (const float*)d_in[2];
    const float* bg0    = (const float*)d_in[3];
    const float* bu0    = (const float*)d_in[4];
    const float* zeta0  = (const float*)d_in[5];
    const float* nu0    = (const float*)d_in[6];
    const float* lambd0 = (const float*)d_in[7];
    const float* gamma0 = (const float*)d_in[8];
    const float* w1     = (const float*)d_in[9];
    const float* u1     = (const float*)d_in[10];
    const float* bg1    = (const float*)d_in[11];
    const float* bu1    = (const float*)d_in[12];
    const float* zeta1  = (const float*)d_in[13];
    const float* nu1    = (const float*)d_in[14];
    const float* lambd1 = (const float*)d_in[15];
    const float* gamma1 = (const float*)d_in[16];

    float* out1 = (float*)d_out;                          // [B,S,H]
    float* hn   = out1 + (size_t)BB * SS * HH;            // [2,B,H]

    zero_flags<<<1, 64>>>();
    fused_grnn<<<2 * BB + NHELP, 512>>>(x,
        u0, w0, bg0, bu0, zeta0, nu0, lambd0, gamma0,
        u1, w1, bg1, bu1, zeta1, nu1, lambd1, gamma1,
        out1, hn);
}

// round 16
// speedup vs baseline: 1.8918x; 1.8918x over previous
#include <cuda_runtime.h>
#include <cstdint>

#define BB 64
#define SS 2048
#define II 64
#define HH 128
#define CH 16
#define NCH (SS/CH)
#define MROWS (BB*SS)

typedef unsigned long long ull;

// Scratch + inter-CTA progress flags (no runtime allocation allowed).
__device__ __align__(256) float g_seq0[(size_t)MROWS * HH];
__device__ unsigned g_flag[BB];

#define BAR_SYNC(id, cnt) asm volatile("bar.sync %0, %1;" :: "r"(id), "r"(cnt) : "memory")

// ---------------- packed f32x2 helpers (sm_100+) ----------------
__device__ __forceinline__ ull packf2(float lo, float hi) {
    ull r; asm("mov.b64 %0, {%1, %2};" : "=l"(r) : "f"(lo), "f"(hi)); return r;
}
__device__ __forceinline__ float2 unpackf2(ull v) {
    float2 r; asm("mov.b64 {%0, %1}, %2;" : "=f"(r.x), "=f"(r.y) : "l"(v)); return r;
}
__device__ __forceinline__ ull ffma2(ull a, ull b, ull c) {
    ull d; asm("fma.rn.f32x2 %0, %1, %2, %3;" : "=l"(d) : "l"(a), "l"(b), "l"(c)); return d;
}
__device__ __forceinline__ ull addf2(ull a, ull b) {
    ull d; asm("add.rn.f32x2 %0, %1, %2;" : "=l"(d) : "l"(a), "l"(b)); return d;
}
__device__ __forceinline__ void lds_v2u64(ull &p0, ull &p1, uint32_t addr) {
    asm volatile("ld.shared.v2.u64 {%0, %1}, [%2];" : "=l"(p0), "=l"(p1) : "r"(addr));
}
__device__ __forceinline__ float ex2f(float x) {
    float r; asm("ex2.approx.ftz.f32 %0, %1;" : "=f"(r) : "f"(x)); return r;
}
__device__ __forceinline__ float rcpf(float x) {
    float r; asm("rcp.approx.ftz.f32 %0, %1;" : "=f"(r) : "f"(x)); return r;
}
__device__ __forceinline__ float sigmoidf_(float x) {
    return rcpf(1.0f + ex2f(-1.4426950408889634f * x));
}
__device__ __forceinline__ unsigned ld_acquire(const unsigned* p) {
    unsigned v;
    asm volatile("ld.acquire.gpu.global.u32 %0, [%1];" : "=r"(v) : "l"(p) : "memory");
    return v;
}
__device__ __forceinline__ void st_release(unsigned* p, unsigned v) {
    asm volatile("st.release.gpu.global.u32 [%0], %1;" :: "l"(p), "r"(v) : "memory");
}

__global__ void zero_flags() {
    if (threadIdx.x < BB) g_flag[threadIdx.x] = 0;
}

// xw_s layout: [parity][col][step], col stride XWCOL floats (16B-aligned pad).
#define XWCOL 20
#define XWBUF (HH * XWCOL)

// ---------------- warp-specialized role, single block barrier per chunk ------
// CTA = one (layer, batch), 512 threads. Iteration n (after bar0, all 512):
//   SCAN (tid>=256, high wids): runs chunk n's CH steps using xw_s[n&1]
//     (16 xw values preloaded via 4 LDS.128). One bar1(256) per step.
//     PROD: fence + bar1 + thread-(s==0) flag release after the chunk.
//   PROJ (tid<256): dots for chunk n+1 from xt[(n+1)&1] -> xw_s[(n+1)&1];
//     then stages rows of chunk n+2 into xt[n&1] (consumer: thread-0-only
//     spin on flag >= (n+3)*CH, bar7 fanout). All buffers parity-disjoint
//     per iteration; bar0 at the top of each iteration publishes everything.
// Synchronization uses ONLY full-count sync barriers (0:512, 1:256, 7:256) —
// no arrive/sync splits, so mismatched-generation deadlock cannot occur.
template<int KF, bool PROD>
__device__ __forceinline__ void role(
    float* hs, float* xt, float* xw_s,
    const float* __restrict__ xsrc,   // rows of width KF
    const float* __restrict__ u,      // [H,H]
    const float* __restrict__ w,      // [KF,H]
    const float* bg, const float* bu,
    const float* zeta, const float* nu,
    const float* lambd, const float* gamma,
    float* __restrict__ outp,         // [S,H] slice
    float* __restrict__ hl,           // [H] slice
    unsigned* flagRel, const unsigned* flagWait)
{
    constexpr int KH   = KF / 2;         // per-thread k-values in proj (32/64)
    constexpr int KHP  = KH + 4;         // padded half width
    constexpr int XROW = 2 * KHP;        // staged row stride (72 or 136)
    constexpr int XTS  = CH * XROW;      // xt buffer stride (floats)
    constexpr int CPR  = KF / 4;         // float4s per row (16 or 32)
    constexpr int RPP  = 256 / CPR;      // rows per load pass (16 or 8)
    constexpr int LPT  = CH / RPP;       // load passes (1 or 2)

    const int tid  = threadIdx.x;
    const int lane = tid & 31;

    if (tid >= 256) {
        // ================= SCAN (high wids) =================
        const int s  = tid - 256;
        const int wp = s >> 5;
        const int q  = lane >> 4;
        const int c  = wp * 16 + (lane & 15);

        ull ureg[32];
#pragma unroll
        for (int m = 0; m < 32; m++) {
            int k0 = 64 * q + 2 * m;
            ureg[m] = packf2(u[(size_t)k0 * HH + c], u[(size_t)(k0 + 1) * HH + c]);
        }
        const float sz = sigmoidf_(zeta[0]);
        const float sn = sigmoidf_(nu[0]);
        float gc = gamma[0];
        gc = fminf(fmaxf(gc, 0.0f), 1.0f);
        const float c1   = (1.0f - gc) * lambd[0];
        const float szsn = sz + sn;
        const float bgs  = -1.4426950408889634f * bg[c];
        const float bus  =  2.8853900817779268f * bu[c];

        const uint32_t hb = (uint32_t)__cvta_generic_to_shared(hs);
        const uint32_t qoffH = (uint32_t)(q * 68 * 4);

        if (s < HH) hs[(s >> 6) * 68 + (s & 63)] = 0.0f;
        float hprev = 0.0f;
        BAR_SYNC(1, 256);

        for (int ch = 0; ch < NCH; ch++) {
            BAR_SYNC(0, 512);                     // chunk boundary
            const float* xwb = xw_s + (size_t)(ch & 1) * XWBUF + (size_t)c * XWCOL;
            float xwv[CH];
#pragma unroll
            for (int k = 0; k < CH / 4; k++) {
                float4 r4 = *reinterpret_cast<const float4*>(xwb + 4 * k);
                xwv[4 * k]     = r4.x;
                xwv[4 * k + 1] = r4.y;
                xwv[4 * k + 2] = r4.z;
                xwv[4 * k + 3] = r4.w;
            }
#pragma unroll
            for (int d = 0; d < CH; d++) {
                const int t = ch * CH + d;
                const uint32_t ra = hb + ((t & 1) ? 544u : 0u) + qoffH;
                ull z0 = packf2(0.f, 0.f);
                ull a0 = z0, a1 = z0, a2 = z0, a3 = z0;
#pragma unroll
                for (int i = 0; i < 8; i++) {
                    ull p0, p1, p2, p3;
                    lds_v2u64(p0, p1, ra + (uint32_t)(i * 32));
                    lds_v2u64(p2, p3, ra + (uint32_t)(i * 32 + 16));
                    a0 = ffma2(p0, ureg[4 * i],     a0);
                    a1 = ffma2(p1, ureg[4 * i + 1], a1);
                    a2 = ffma2(p2, ureg[4 * i + 2], a2);
                    a3 = ffma2(p3, ureg[4 * i + 3], a3);
                }
                float2 f = unpackf2(addf2(addf2(a0, a1), addf2(a2, a3)));
                float part = f.x + f.y;
                float pre = part + __shfl_xor_sync(0xffffffffu, part, 16) + xwv[d];

                float z  = rcpf(1.0f + ex2f(fmaf(-1.4426950408889634f, pre, bgs)));
                float hh = 1.0f - 2.0f * rcpf(1.0f + ex2f(fmaf(2.8853900817779268f, pre, bus)));
                float t1 = fmaf(-sz, hh, hprev);
                float hn = fmaf(z, t1, szsn * hh);
                float hc = fmaf(gc, hn, c1);

                if (lane < 16) {
                    hs[((t & 1) ^ 1) * 136 + (c >> 6) * 68 + (c & 63)] = hc;
                    outp[(size_t)t * HH + c] = hc;
                }
                hprev = hc;
                BAR_SYNC(1, 256);
            }
            if (PROD) {
                __threadfence();
                BAR_SYNC(1, 256);
                if (s == 0) st_release(flagRel, (unsigned)((ch + 1) * CH));
            }
        }
        if (lane < 16) hl[c] = hprev;
    } else {
        // ================= PROJ (low wids) =================
        const int wp2 = tid >> 5;
        const int qp  = lane >> 4;
        const int cp  = wp2 * 16 + (lane & 15);

        ull wreg[KH / 2];
#pragma unroll
        for (int m = 0; m < KH / 2; m++) {
            int k0 = KH * qp + 2 * m;
            wreg[m] = packf2(w[(size_t)k0 * HH + cp], w[(size_t)(k0 + 1) * HH + cp]);
        }

        const int rowd = tid / CPR;          // row within a pass
        const int e    = (tid % CPR) * 4;    // float column within row
        const int eq   = e / KH, ew = e % KH;
        const uint32_t xb = (uint32_t)__cvta_generic_to_shared(xt);

        // ---- prologue: stage chunk 0 -> xt[0], chunk 1 -> xt[1], dots chunk 0
#pragma unroll
        for (int pc = 0; pc < 2; pc++) {
            if (!PROD) {
                if (tid == 0) {
                    while (ld_acquire(flagWait) < (unsigned)((pc + 1) * CH)) { }
                }
                BAR_SYNC(7, 256);
            }
            float4 s4[LPT];
#pragma unroll
            for (int l = 0; l < LPT; l++)
                s4[l] = __ldcg(reinterpret_cast<const float4*>(
                    xsrc + (size_t)(pc * CH + l * RPP + rowd) * KF + e));
#pragma unroll
            for (int l = 0; l < LPT; l++)
                *reinterpret_cast<float4*>(
                    &xt[pc * XTS + (l * RPP + rowd) * XROW + eq * KHP + ew]) = s4[l];
        }
        BAR_SYNC(7, 256);                    // staging visible to dot threads
        {
            const uint32_t tb = xb + (uint32_t)(qp * KHP * 4);
            float* xwdst = xw_s + (size_t)cp * XWCOL;
#pragma unroll
            for (int d = 0; d < CH; d++) {
                const uint32_t base = tb + (uint32_t)(d * XROW * 4);
                ull z0 = packf2(0.f, 0.f);
                ull b0 = z0, b1 = z0, b2 = z0, b3 = z0;
#pragma unroll
                for (int i = 0; i < KH / 8; i++) {
                    ull p0, p1, p2, p3;
                    lds_v2u64(p0, p1, base + (uint32_t)(i * 32));
                    lds_v2u64(p2, p3, base + (uint32_t)(i * 32 + 16));
                    b0 = ffma2(p0, wreg[4 * i],     b0);
                    b1 = ffma2(p1, wreg[4 * i + 1], b1);
                    b2 = ffma2(p2, wreg[4 * i + 2], b2);
                    b3 = ffma2(p3, wreg[4 * i + 3], b3);
                }
                float2 f = unpackf2(addf2(addf2(b0, b1), addf2(b2, b3)));
                float pp = f.x + f.y;
                pp += __shfl_xor_sync(0xffffffffu, pp, 16);
                if (lane < 16) xwdst[d] = pp;
            }
        }

        // ---- main loop
        for (int ch = 0; ch < NCH; ch++) {
            BAR_SYNC(0, 512);                     // chunk boundary
            // dots for chunk ch+1 from xt[(ch+1)&1] -> xw_s[(ch+1)&1]
            if (ch + 1 < NCH) {
                const int pn = (ch + 1) & 1;
                const uint32_t tb = xb + (uint32_t)(pn * XTS * 4) + (uint32_t)(qp * KHP * 4);
                float* xwdst = xw_s + (size_t)pn * XWBUF + (size_t)cp * XWCOL;
#pragma unroll
                for (int d = 0; d < CH; d++) {
                    const uint32_t base = tb + (uint32_t)(d * XROW * 4);
                    ull z0 = packf2(0.f, 0.f);
                    ull b0 = z0, b1 = z0, b2 = z0, b3 = z0;
#pragma unroll
                    for (int i = 0; i < KH / 8; i++) {
                        ull p0, p1, p2, p3;
                        lds_v2u64(p0, p1, base + (uint32_t)(i * 32));
                        lds_v2u64(p2, p3, base + (uint32_t)(i * 32 + 16));
                        b0 = ffma2(p0, wreg[4 * i],     b0);
                        b1 = ffma2(p1, wreg[4 * i + 1], b1);
                        b2 = ffma2(p2, wreg[4 * i + 2], b2);
                        b3 = ffma2(p3, wreg[4 * i + 3], b3);
                    }
                    float2 f = unpackf2(addf2(addf2(b0, b1), addf2(b2, b3)));
                    float pp = f.x + f.y;
                    pp += __shfl_xor_sync(0xffffffffu, pp, 16);
                    if (lane < 16) xwdst[d] = pp;
                }
            }
            // stage rows of chunk ch+2 into xt[ch&1] (read by dots in iter ch+1)
            if (ch + 2 < NCH) {
                if (!PROD) {
                    if (tid == 0) {
                        while (ld_acquire(flagWait) < (unsigned)((ch + 3) * CH)) { }
                    }
                    BAR_SYNC(7, 256);
                }
                float4 s4[LPT];
#pragma unroll
                for (int l = 0; l < LPT; l++)
                    s4[l] = __ldcg(reinterpret_cast<const float4*>(
                        xsrc + (size_t)((ch + 2) * CH + l * RPP + rowd) * KF + e));
#pragma unroll
                for (int l = 0; l < LPT; l++)
                    *reinterpret_cast<float4*>(
                        &xt[(ch & 1) * XTS + (l * RPP + rowd) * XROW + eq * KHP + ew]) = s4[l];
            }
        }
    }
}

// ---------------- fused persistent kernel: 64 producer + 64 consumer CTAs
__global__ void __launch_bounds__(512, 1) fused_grnn(
    const float* __restrict__ x,
    const float* __restrict__ u0, const float* __restrict__ w0,
    const float* __restrict__ bg0, const float* __restrict__ bu0,
    const float* __restrict__ zeta0, const float* __restrict__ nu0,
    const float* __restrict__ lambd0, const float* __restrict__ gamma0,
    const float* __restrict__ u1, const float* __restrict__ w1,
    const float* __restrict__ bg1, const float* __restrict__ bu1,
    const float* __restrict__ zeta1, const float* __restrict__ nu1,
    const float* __restrict__ lambd1, const float* __restrict__ gamma1,
    float* __restrict__ out1, float* __restrict__ hn)
{
    __shared__ __align__(16) float hs[2 * 136];
    __shared__ __align__(16) float xt[2 * CH * 136];    // sized for KF=128
    __shared__ __align__(16) float xw_s[2 * XWBUF];

    const int rank = blockIdx.x;
    if (rank < BB) {
        const int b = rank;
        role<II, true>(hs, xt, xw_s,
            x + (size_t)b * SS * II, u0, w0,
            bg0, bu0, zeta0, nu0, lambd0, gamma0,
            g_seq0 + (size_t)b * SS * HH,
            hn + (size_t)b * HH,
            &g_flag[b], nullptr);
    } else {
        const int b = rank - BB;
        role<HH, false>(hs, xt, xw_s,
            g_seq0 + (size_t)b * SS * HH, u1, w1,
            bg1, bu1, zeta1, nu1, lambd1, gamma1,
            out1 + (size_t)b * SS * HH,
            hn + (size_t)(BB + b) * HH,
            nullptr, &g_flag[b]);
    }
}

// ---------------- launch ----------------
extern "C" void kernel_launch(void* const* d_in, const int* in_sizes, int n_in,
                              void* d_out, int out_size)
{
    const float* x      = (const float*)d_in[0];
    const float* w0     = (const float*)d_in[1];
    const float* u0     = (const float*)d_in[2];
    const float* bg0    = (const float*)d_in[3];
    const float* bu0    = (const float*)d_in[4];
    const float* zeta0  = (const float*)d_in[5];
    const float* nu0    = (const float*)d_in[6];
    const float* lambd0 = (const float*)d_in[7];
    const float* gamma0 = (const float*)d_in[8];
    const float* w1     = (const float*)d_in[9];
    const float* u1     = (const float*)d_in[10];
    const float* bg1    = (const float*)d_in[11];
    const float* bu1    = (const float*)d_in[12];
    const float* zeta1  = (const float*)d_in[13];
    const float* nu1    = (const float*)d_in[14];
    const float* lambd1 = (const float*)d_in[15];
    const float* gamma1 = (const float*)d_in[16];

    float* out1 = (float*)d_out;                          // [B,S,H]
    float* hn   = out1 + (size_t)BB * SS * HH;            // [2,B,H]

    zero_flags<<<1, 64>>>();
    fused_grnn<<<2 * BB, 512>>>(x,
        u0, w0, bg0, bu0, zeta0, nu0, lambd0, gamma0,
        u1, w1, bg1, bu1, zeta1, nu1, lambd1, gamma1,
        out1, hn);
}